// round 2
// baseline (speedup 1.0000x reference)
#include <cuda_runtime.h>
#include <math.h>

#define NB 64
#define NL 64
#define ND 512
#define TEMP1 4.0f
#define TEMP2 5.0f
#define TEMP3 10.0f
#define EPSV 1e-8f

// Scratch (allocation-free rule: __device__ globals)
__device__ float Gg[NB * NL * NL];   // Gram matrices per j: 1 MB
__device__ float w1g[NB * NL];       // ||sent[i,q]||
__device__ float simg[NB * NB];      // sim[j][i]

// ---------------------------------------------------------------------------
// w1: row norms of sent (4096 rows of 512). One warp per row.
__global__ void w1_kernel(const float* __restrict__ sent) {
    int row = blockIdx.x * 8 + (threadIdx.x >> 5);
    int lane = threadIdx.x & 31;
    const float* p = sent + (size_t)row * ND;
    float s = 0.f;
    #pragma unroll
    for (int d = lane; d < ND; d += 32) { float v = p[d]; s += v * v; }
    #pragma unroll
    for (int o = 16; o; o >>= 1) s += __shfl_xor_sync(0xffffffffu, s, o);
    if (lane == 0) w1g[row] = sqrtf(s);
}

// ---------------------------------------------------------------------------
// Gram: G_j = ecg_j @ ecg_j^T  (64x64x512), one CTA per j.
__global__ void __launch_bounds__(256) gram_kernel(const float* __restrict__ ecg) {
    __shared__ float tile[64][68];
    int j = blockIdx.x;
    int tid = threadIdx.x;
    int tx = tid & 15, ty = tid >> 4;
    const float* E = ecg + (size_t)j * NL * ND;

    float acc[4][4] = {};
    for (int kc = 0; kc < ND; kc += 64) {
        __syncthreads();
        for (int n = tid; n < 64 * 64; n += 256) {
            int r = n >> 6, d = n & 63;
            tile[d][r] = E[r * ND + kc + d];   // transposed store
        }
        __syncthreads();
        #pragma unroll 8
        for (int d = 0; d < 64; d++) {
            float4 a = *(const float4*)&tile[d][ty * 4];
            float4 b = *(const float4*)&tile[d][tx * 4];
            acc[0][0] += a.x * b.x; acc[0][1] += a.x * b.y; acc[0][2] += a.x * b.z; acc[0][3] += a.x * b.w;
            acc[1][0] += a.y * b.x; acc[1][1] += a.y * b.y; acc[1][2] += a.y * b.z; acc[1][3] += a.y * b.w;
            acc[2][0] += a.z * b.x; acc[2][1] += a.z * b.y; acc[2][2] += a.z * b.z; acc[2][3] += a.z * b.w;
            acc[3][0] += a.w * b.x; acc[3][1] += a.w * b.y; acc[3][2] += a.w * b.z; acc[3][3] += a.w * b.w;
        }
    }
    float* Gj = Gg + (size_t)j * NL * NL;
    #pragma unroll
    for (int ss = 0; ss < 4; ss++)
        #pragma unroll
        for (int qq = 0; qq < 4; qq++)
            Gj[(ty * 4 + ss) * NL + tx * 4 + qq] = acc[ss][qq];
}

// ---------------------------------------------------------------------------
// Main fused kernel: one CTA per (i, j) pair.
//   S = ecg_j @ sent_i^T (64x64), softmax over q, transposed softmax over s,
//   w12, w2 via Gram, sim entry, att_maps for diagonal pairs.
__global__ void __launch_bounds__(256) pair_kernel(const float* __restrict__ ecg,
                                                   const float* __restrict__ sent,
                                                   float* __restrict__ out) {
    __shared__ float bufE[64][68];  // Etile -> S -> G
    __shared__ float bufQ[64][68];  // Qtile -> attn1 -> A (transposed, [q][s])
    __shared__ float w12s[64];
    __shared__ float w2sqs[64];
    __shared__ float ssum;

    int i = blockIdx.x;  // sent batch index
    int j = blockIdx.y;  // ecg batch index
    int tid = threadIdx.x;
    int tx = tid & 15, ty = tid >> 4;

    const float* E = ecg + (size_t)j * NL * ND;
    const float* Q = sent + (size_t)i * NL * ND;

    // ---- GEMM: S[s][q] = sum_d E[s][d] * Q[q][d]
    float acc[4][4] = {};
    for (int kc = 0; kc < ND; kc += 64) {
        __syncthreads();
        for (int n = tid; n < 64 * 64; n += 256) {
            int r = n >> 6, d = n & 63;
            bufE[d][r] = E[r * ND + kc + d];
            bufQ[d][r] = Q[r * ND + kc + d];
        }
        __syncthreads();
        #pragma unroll 8
        for (int d = 0; d < 64; d++) {
            float4 a = *(const float4*)&bufE[d][ty * 4];
            float4 b = *(const float4*)&bufQ[d][tx * 4];
            acc[0][0] += a.x * b.x; acc[0][1] += a.x * b.y; acc[0][2] += a.x * b.z; acc[0][3] += a.x * b.w;
            acc[1][0] += a.y * b.x; acc[1][1] += a.y * b.y; acc[1][2] += a.y * b.z; acc[1][3] += a.y * b.w;
            acc[2][0] += a.z * b.x; acc[2][1] += a.z * b.y; acc[2][2] += a.z * b.z; acc[2][3] += a.z * b.w;
            acc[3][0] += a.w * b.x; acc[3][1] += a.w * b.y; acc[3][2] += a.w * b.z; acc[3][3] += a.w * b.w;
        }
    }
    __syncthreads();
    // write S to bufE: S[s][q]
    #pragma unroll
    for (int ss = 0; ss < 4; ss++)
        #pragma unroll
        for (int qq = 0; qq < 4; qq++)
            bufE[ty * 4 + ss][tx * 4 + qq] = acc[ss][qq];
    if (tid < 64) w2sqs[tid] = 0.f;
    if (tid == 0) ssum = 0.f;
    __syncthreads();

    // ---- softmax 1: over q, per row s.  attn1[s][q] -> bufQ[s][q]
    {
        int g = tid >> 2, l = tid & 3;  // row g, 4 threads per row
        float v[16];
        float mx = -1e30f;
        #pragma unroll
        for (int m = 0; m < 16; m++) { v[m] = bufE[g][l * 16 + m]; mx = fmaxf(mx, v[m]); }
        mx = fmaxf(mx, __shfl_xor_sync(0xffffffffu, mx, 1));
        mx = fmaxf(mx, __shfl_xor_sync(0xffffffffu, mx, 2));
        float sm = 0.f;
        #pragma unroll
        for (int m = 0; m < 16; m++) { v[m] = __expf(v[m] - mx); sm += v[m]; }
        sm += __shfl_xor_sync(0xffffffffu, sm, 1);
        sm += __shfl_xor_sync(0xffffffffu, sm, 2);
        float inv = 1.f / sm;
        #pragma unroll
        for (int m = 0; m < 16; m++) bufQ[g][l * 16 + m] = v[m] * inv;
    }
    __syncthreads();

    // ---- softmax 2 (over s, per q) with in-place transpose: A[q][s] -> bufQ[q][s]
    float e[16];
    float invs;
    {
        int q = tid >> 2, l = tid & 3;
        float mx = -1e30f;
        #pragma unroll
        for (int m = 0; m < 16; m++) { e[m] = TEMP1 * bufQ[l * 16 + m][q]; mx = fmaxf(mx, e[m]); }
        mx = fmaxf(mx, __shfl_xor_sync(0xffffffffu, mx, 1));
        mx = fmaxf(mx, __shfl_xor_sync(0xffffffffu, mx, 2));
        float sm = 0.f;
        #pragma unroll
        for (int m = 0; m < 16; m++) { e[m] = __expf(e[m] - mx); sm += e[m]; }
        sm += __shfl_xor_sync(0xffffffffu, sm, 1);
        sm += __shfl_xor_sync(0xffffffffu, sm, 2);
        invs = 1.f / sm;
    }
    __syncthreads();  // all reads of attn1 complete before overwrite
    {
        int q = tid >> 2, l = tid & 3;
        float w12p = 0.f;
        #pragma unroll
        for (int m = 0; m < 16; m++) {
            int s = l * 16 + m;
            float a = e[m] * invs;
            bufQ[q][s] = a;
            w12p += a * bufE[s][q];  // S[s][q]
        }
        w12p += __shfl_xor_sync(0xffffffffu, w12p, 1);
        w12p += __shfl_xor_sync(0xffffffffu, w12p, 2);
        if (l == 0) w12s[q] = w12p;
    }
    __syncthreads();

    // ---- load G_j into bufE (S no longer needed)
    const float* Gj = Gg + (size_t)j * NL * NL;
    for (int n = tid; n < 64 * 64; n += 256) bufE[n >> 6][n & 63] = Gj[n];
    __syncthreads();

    // ---- M = A @ G_j ; w2sq[q] = sum_t M[q][t] * A[q][t]
    {
        float acc2[4][4] = {};
        #pragma unroll 8
        for (int u = 0; u < 64; u++) {
            float a0 = bufQ[ty * 4 + 0][u];
            float a1 = bufQ[ty * 4 + 1][u];
            float a2 = bufQ[ty * 4 + 2][u];
            float a3 = bufQ[ty * 4 + 3][u];
            float4 b = *(const float4*)&bufE[u][tx * 4];
            acc2[0][0] += a0 * b.x; acc2[0][1] += a0 * b.y; acc2[0][2] += a0 * b.z; acc2[0][3] += a0 * b.w;
            acc2[1][0] += a1 * b.x; acc2[1][1] += a1 * b.y; acc2[1][2] += a1 * b.z; acc2[1][3] += a1 * b.w;
            acc2[2][0] += a2 * b.x; acc2[2][1] += a2 * b.y; acc2[2][2] += a2 * b.z; acc2[2][3] += a2 * b.w;
            acc2[3][0] += a3 * b.x; acc2[3][1] += a3 * b.y; acc2[3][2] += a3 * b.z; acc2[3][3] += a3 * b.w;
        }
        #pragma unroll
        for (int ss = 0; ss < 4; ss++) {
            int q = ty * 4 + ss;
            float p = 0.f;
            #pragma unroll
            for (int qq = 0; qq < 4; qq++) p += acc2[ss][qq] * bufQ[q][tx * 4 + qq];
            atomicAdd(&w2sqs[q], p);
        }
    }
    __syncthreads();

    // ---- cos, partial logsumexp-over-q
    if (tid < 64) {
        int q = tid;
        float w2 = sqrtf(w2sqs[q]);
        float cosv = w12s[q] / fmaxf(w1g[i * NL + q] * w2, EPSV);
        atomicAdd(&ssum, __expf(TEMP2 * cosv));
    }
    __syncthreads();
    if (tid == 0) simg[j * NB + i] = TEMP3 * logf(ssum);

    // ---- att_maps for diagonal pairs: attn[i,i][q][s]
    if (i == j) {
        float* om = out + 1 + (size_t)i * NL * NL;
        for (int n = tid; n < 64 * 64; n += 256) om[n] = bufQ[n >> 6][n & 63];
    }
}

// ---------------------------------------------------------------------------
// Loss: symmetric log-softmax on 64x64 sim, diagonal mean. 1 CTA, 64 threads.
__global__ void loss_kernel(float* __restrict__ out) {
    __shared__ float acc0;
    int b = threadIdx.x;
    if (b == 0) acc0 = 0.f;
    __syncthreads();
    float mr = -1e30f, mc = -1e30f;
    for (int k = 0; k < NB; k++) {
        mr = fmaxf(mr, simg[b * NB + k]);
        mc = fmaxf(mc, simg[k * NB + b]);
    }
    float sr = 0.f, sc = 0.f;
    for (int k = 0; k < NB; k++) {
        sr += expf(simg[b * NB + k] - mr);
        sc += expf(simg[k * NB + b] - mc);
    }
    float diag = simg[b * NB + b];
    float lp0 = diag - mr - logf(sr);
    float lp1 = diag - mc - logf(sc);
    atomicAdd(&acc0, lp0 + lp1);
    __syncthreads();
    if (b == 0) out[0] = -acc0 / (2.0f * (float)NB);
}

// ---------------------------------------------------------------------------
extern "C" void kernel_launch(void* const* d_in, const int* in_sizes, int n_in,
                              void* d_out, int out_size) {
    const float* ecg = (const float*)d_in[0];   // (64, 64, 512) fp32
    const float* sent = (const float*)d_in[1];  // (64, 64, 512) fp32
    float* out = (float*)d_out;                 // [loss, att_maps(64*64*64)]

    w1_kernel<<<NB * NL / 8, 256>>>(sent);
    gram_kernel<<<NB, 256>>>(ecg);
    dim3 grid(NB, NB);
    pair_kernel<<<grid, 256>>>(ecg, sent, out);
    loss_kernel<<<1, NB>>>(out);
}

// round 5
// speedup vs baseline: 1.5802x; 1.5802x over previous
#include <cuda_runtime.h>
#include <cuda_fp16.h>
#include <math.h>
#include <stdint.h>

#define NB 64
#define NL 64
#define ND 512
#define TEMP1 4.0f
#define TEMP2 5.0f
#define TEMP3 10.0f
#define EPSV 1e-8f

// ---------------- scratch (__device__ globals; no allocation allowed) -------
__device__ float Gg[NB * NL * NL];
__device__ float w1g[NB * NL];
__device__ float simg[NB * NB];
__device__ __half eh_g[4096 * 512];  // fp16 hi/lo splits, plain row-major
__device__ __half el_g[4096 * 512];
__device__ __half sh_g[4096 * 512];
__device__ __half sl_g[4096 * 512];

// ---------------- PTX helpers (baseline ISA only: sm_80-era) ----------------
__device__ __forceinline__ uint32_t smem_u32(const void* p) {
    return (uint32_t)__cvta_generic_to_shared(p);
}
__device__ __forceinline__ void cp16(uint32_t dst, const void* src) {
    asm volatile("cp.async.cg.shared.global [%0], [%1], 16;" :: "r"(dst), "l"(src));
}
#define CP_COMMIT() asm volatile("cp.async.commit_group;" ::: "memory")
#define CP_WAIT1()  asm volatile("cp.async.wait_group 1;" ::: "memory")
#define CP_WAIT0()  asm volatile("cp.async.wait_group 0;" ::: "memory")

__device__ __forceinline__ void ldsm4(uint32_t* r, uint32_t a) {
    asm volatile("ldmatrix.sync.aligned.m8n8.x4.shared.b16 {%0,%1,%2,%3}, [%4];"
        : "=r"(r[0]), "=r"(r[1]), "=r"(r[2]), "=r"(r[3]) : "r"(a));
}
__device__ __forceinline__ void mma16816(float* d, const uint32_t* a, const uint32_t* b) {
    asm volatile(
        "mma.sync.aligned.m16n8k16.row.col.f32.f16.f16.f32 "
        "{%0,%1,%2,%3}, {%4,%5,%6,%7}, {%8,%9}, {%0,%1,%2,%3};"
        : "+f"(d[0]), "+f"(d[1]), "+f"(d[2]), "+f"(d[3])
        : "r"(a[0]), "r"(a[1]), "r"(a[2]), "r"(a[3]), "r"(b[0]), "r"(b[1]));
}

// ---------------------------------------------------------------------------
// convert: fp32 -> fp16 hi + fp16 lo residual. 4 floats per thread.
__global__ void __launch_bounds__(256) convert_kernel(const float4* __restrict__ ecg,
                                                      const float4* __restrict__ sent) {
    int n = blockIdx.x * 256 + threadIdx.x;   // 0..524287
    float4 a = ecg[n];
    ushort4 h, l;
    {
        __half t;
        t = __float2half_rn(a.x); h.x = __half_as_ushort(t); l.x = __half_as_ushort(__float2half_rn(a.x - __half2float(t)));
        t = __float2half_rn(a.y); h.y = __half_as_ushort(t); l.y = __half_as_ushort(__float2half_rn(a.y - __half2float(t)));
        t = __float2half_rn(a.z); h.z = __half_as_ushort(t); l.z = __half_as_ushort(__float2half_rn(a.z - __half2float(t)));
        t = __float2half_rn(a.w); h.w = __half_as_ushort(t); l.w = __half_as_ushort(__float2half_rn(a.w - __half2float(t)));
    }
    ((ushort4*)eh_g)[n] = h;
    ((ushort4*)el_g)[n] = l;

    float4 b = sent[n];
    {
        __half t;
        t = __float2half_rn(b.x); h.x = __half_as_ushort(t); l.x = __half_as_ushort(__float2half_rn(b.x - __half2float(t)));
        t = __float2half_rn(b.y); h.y = __half_as_ushort(t); l.y = __half_as_ushort(__float2half_rn(b.y - __half2float(t)));
        t = __float2half_rn(b.z); h.z = __half_as_ushort(t); l.z = __half_as_ushort(__float2half_rn(b.z - __half2float(t)));
        t = __float2half_rn(b.w); h.w = __half_as_ushort(t); l.w = __half_as_ushort(__float2half_rn(b.w - __half2float(t)));
    }
    ((ushort4*)sh_g)[n] = h;
    ((ushort4*)sl_g)[n] = l;
}

// ---------------------------------------------------------------------------
__global__ void w1_kernel(const float* __restrict__ sent) {
    int row = blockIdx.x * 8 + (threadIdx.x >> 5);
    int lane = threadIdx.x & 31;
    const float* p = sent + (size_t)row * ND;
    float s = 0.f;
    #pragma unroll
    for (int d = lane; d < ND; d += 32) { float v = p[d]; s += v * v; }
    #pragma unroll
    for (int o = 16; o; o >>= 1) s += __shfl_xor_sync(0xffffffffu, s, o);
    if (lane == 0) w1g[row] = sqrtf(s);
}

// ---------------------------------------------------------------------------
__global__ void __launch_bounds__(256) gram_kernel(const float* __restrict__ ecg) {
    __shared__ float tile[64][68];
    int j = blockIdx.x;
    int tid = threadIdx.x;
    int tx = tid & 15, ty = tid >> 4;
    const float* E = ecg + (size_t)j * NL * ND;

    float acc[4][4] = {};
    for (int kc = 0; kc < ND; kc += 64) {
        __syncthreads();
        for (int n = tid; n < 64 * 64; n += 256) {
            int r = n >> 6, d = n & 63;
            tile[d][r] = E[r * ND + kc + d];
        }
        __syncthreads();
        #pragma unroll 8
        for (int d = 0; d < 64; d++) {
            float4 a = *(const float4*)&tile[d][ty * 4];
            float4 b = *(const float4*)&tile[d][tx * 4];
            acc[0][0] += a.x * b.x; acc[0][1] += a.x * b.y; acc[0][2] += a.x * b.z; acc[0][3] += a.x * b.w;
            acc[1][0] += a.y * b.x; acc[1][1] += a.y * b.y; acc[1][2] += a.y * b.z; acc[1][3] += a.y * b.w;
            acc[2][0] += a.z * b.x; acc[2][1] += a.z * b.y; acc[2][2] += a.z * b.z; acc[2][3] += a.z * b.w;
            acc[3][0] += a.w * b.x; acc[3][1] += a.w * b.y; acc[3][2] += a.w * b.z; acc[3][3] += a.w * b.w;
        }
    }
    float* Gj = Gg + (size_t)j * NL * NL;
    #pragma unroll
    for (int ss = 0; ss < 4; ss++)
        #pragma unroll
        for (int qq = 0; qq < 4; qq++)
            Gj[(ty * 4 + ss) * NL + tx * 4 + qq] = acc[ss][qq];
}

// ---------------------------------------------------------------------------
// pair_kernel: CTA = (bi, bj); 128 ecg rows (j = 2bj+jh) x 128 sent rows
// (i = 2bi+ih). fp16x3 mma.sync GEMM -> S in smem -> epilogue for 4 pairs.
#define STAGE 16384
#define SROW 133
#define DSMEM_BYTES (2 * STAGE + 128 * SROW * 4)

__global__ void __launch_bounds__(256, 2) pair_kernel(float* __restrict__ out) {
    extern __shared__ char dsm[];
    __shared__ float w12s[64];
    __shared__ float w2sqs[64];
    __shared__ float ssum;

    uint32_t base = smem_u32(dsm);
    float* S    = (float*)(dsm + 2 * STAGE);    // 128 x 133 fp32
    float* bufG = (float*)dsm;                  // 64 x 64 (overlays stage 0)
    float* bufQ = (float*)(dsm + STAGE);        // 64 x 64 (overlays stage 1)

    int tid = threadIdx.x;
    int wid = tid >> 5, lane = tid & 31;
    int bi = blockIdx.x, bj = blockIdx.y;
    int wm = wid & 1, wn = wid >> 1;

    const char* ehp = (const char*)eh_g;
    const char* elp = (const char*)el_g;
    const char* shp = (const char*)sh_g;
    const char* slp = (const char*)sl_g;
    size_t aoff = (size_t)(128 * bj) * 1024;    // bytes (row = 512 halfs = 1024B)
    size_t boff = (size_t)(128 * bi) * 1024;

    // ldmatrix lane offsets (swizzle: seg ^= (row>>2)&1, 32B rows)
    int q4 = lane >> 3;
    int ar = (lane & 7) + (q4 & 1) * 8;
    int as = q4 >> 1;
    uint32_t offA = (uint32_t)((wm * 64 + ar) * 32 + ((as ^ ((ar >> 2) & 1)) * 16));
    int br = (lane & 7) + ((q4 >> 1) & 1) * 8;
    int bs = q4 & 1;
    uint32_t offB = (uint32_t)((wn * 32 + br) * 32 + ((bs ^ ((br >> 2) & 1)) * 16));

    // cp.async lane params: one 16B unit per matrix per thread
    int cr = tid >> 1, cs = tid & 1;
    uint32_t cdst = (uint32_t)((cr * 2 + (cs ^ ((cr >> 2) & 1))) * 16);
    size_t csrc = (size_t)cr * 1024 + (size_t)cs * 16;

    float acc[4][4][4] = {};

    auto copy_chunk = [&](uint32_t st, int kc) {
        size_t ks = (size_t)kc * 32;
        cp16(st + cdst,          ehp + aoff + csrc + ks);
        cp16(st + 4096 + cdst,   elp + aoff + csrc + ks);
        cp16(st + 8192 + cdst,   shp + boff + csrc + ks);
        cp16(st + 12288 + cdst,  slp + boff + csrc + ks);
        CP_COMMIT();
    };

    copy_chunk(base, 0);
    copy_chunk(base + STAGE, 1);

    for (int c = 0; c < 32; c++) {
        if (c < 30) CP_WAIT1(); else CP_WAIT0();
        __syncthreads();
        uint32_t st = base + (uint32_t)(c & 1) * STAGE;
        {
            uint32_t af[4][4], bh[2][4], bl[2][4];
            // B is [n][k] with k contiguous == col-major KxN: NON-transposed ldmatrix
            ldsm4(bh[0], st + 8192 + offB);
            ldsm4(bh[1], st + 8192 + offB + 512);
            ldsm4(bl[0], st + 12288 + offB);
            ldsm4(bl[1], st + 12288 + offB + 512);
            #pragma unroll
            for (int f = 0; f < 4; f++) ldsm4(af[f], st + offA + f * 512);
            #pragma unroll
            for (int f = 0; f < 4; f++)
                #pragma unroll
                for (int g = 0; g < 4; g++) {
                    mma16816(acc[f][g], af[f], &bh[g >> 1][(g & 1) * 2]);
                    mma16816(acc[f][g], af[f], &bl[g >> 1][(g & 1) * 2]);
                }
            #pragma unroll
            for (int f = 0; f < 4; f++) ldsm4(af[f], st + 4096 + offA + f * 512);
            #pragma unroll
            for (int f = 0; f < 4; f++)
                #pragma unroll
                for (int g = 0; g < 4; g++)
                    mma16816(acc[f][g], af[f], &bh[g >> 1][(g & 1) * 2]);
        }
        __syncthreads();
        if (c + 2 < 32) copy_chunk(st, c + 2);
    }

    // ---- write S (scores, fp32) to smem
    {
        int r0 = lane >> 2, c0 = (lane & 3) * 2;
        #pragma unroll
        for (int f = 0; f < 4; f++)
            #pragma unroll
            for (int g = 0; g < 4; g++) {
                float* p = S + (size_t)(wm * 64 + f * 16 + r0) * SROW + wn * 32 + g * 8 + c0;
                p[0] = acc[f][g][0];
                p[1] = acc[f][g][1];
                p[8 * SROW] = acc[f][g][2];
                p[8 * SROW + 1] = acc[f][g][3];
            }
    }
    __syncthreads();

    // ---- epilogue: 4 (i,j) pairs
    int tx = tid & 15, ty = tid >> 4;
    for (int p = 0; p < 4; p++) {
        int jh = p >> 1, ih = p & 1;
        int i = 2 * bi + ih;
        int j = 2 * bj + jh;
        const float* Sp = S + (size_t)(64 * jh) * SROW + 64 * ih;  // S[s][q]

        if (ih == 0) {
            const float* Gj = Gg + (size_t)j * NL * NL;
            for (int n = tid; n < 64 * 64; n += 256) bufG[n] = Gj[n];
        }
        if (tid < 64) w2sqs[tid] = 0.f;
        if (tid == 0) ssum = 0.f;
        __syncthreads();

        // softmax 1 over q (per row s): attn1[s][q] -> bufQ
        {
            int g = tid >> 2, l = tid & 3;
            float v[16];
            float mx = -1e30f;
            #pragma unroll
            for (int m = 0; m < 16; m++) { v[m] = Sp[g * SROW + l * 16 + m]; mx = fmaxf(mx, v[m]); }
            mx = fmaxf(mx, __shfl_xor_sync(0xffffffffu, mx, 1));
            mx = fmaxf(mx, __shfl_xor_sync(0xffffffffu, mx, 2));
            float sm = 0.f;
            #pragma unroll
            for (int m = 0; m < 16; m++) { v[m] = __expf(v[m] - mx); sm += v[m]; }
            sm += __shfl_xor_sync(0xffffffffu, sm, 1);
            sm += __shfl_xor_sync(0xffffffffu, sm, 2);
            float inv = 1.f / sm;
            #pragma unroll
            for (int m = 0; m < 16; m++) bufQ[g * 64 + l * 16 + m] = v[m] * inv;
        }
        __syncthreads();

        // softmax 2 over s (transposed): A[q][s] -> bufQ, plus w12
        float e[16];
        float invs;
        {
            int q = tid >> 2, l = tid & 3;
            float mx = -1e30f;
            #pragma unroll
            for (int m = 0; m < 16; m++) { e[m] = TEMP1 * bufQ[(l * 16 + m) * 64 + q]; mx = fmaxf(mx, e[m]); }
            mx = fmaxf(mx, __shfl_xor_sync(0xffffffffu, mx, 1));
            mx = fmaxf(mx, __shfl_xor_sync(0xffffffffu, mx, 2));
            float sm = 0.f;
            #pragma unroll
            for (int m = 0; m < 16; m++) { e[m] = __expf(e[m] - mx); sm += e[m]; }
            sm += __shfl_xor_sync(0xffffffffu, sm, 1);
            sm += __shfl_xor_sync(0xffffffffu, sm, 2);
            invs = 1.f / sm;
        }
        __syncthreads();
        {
            int q = tid >> 2, l = tid & 3;
            float w12p = 0.f;
            #pragma unroll
            for (int m = 0; m < 16; m++) {
                int s = l * 16 + m;
                float a = e[m] * invs;
                bufQ[q * 64 + s] = a;
                w12p += a * Sp[s * SROW + q];
            }
            w12p += __shfl_xor_sync(0xffffffffu, w12p, 1);
            w12p += __shfl_xor_sync(0xffffffffu, w12p, 2);
            if (l == 0) w12s[q] = w12p;
        }
        __syncthreads();

        // w2sq[q] = diag(A G A^T)
        {
            float acc2[4][4] = {};
            #pragma unroll 8
            for (int u = 0; u < 64; u++) {
                float a0 = bufQ[(ty * 4 + 0) * 64 + u];
                float a1 = bufQ[(ty * 4 + 1) * 64 + u];
                float a2 = bufQ[(ty * 4 + 2) * 64 + u];
                float a3 = bufQ[(ty * 4 + 3) * 64 + u];
                float4 b = *(const float4*)&bufG[u * 64 + tx * 4];
                acc2[0][0] += a0 * b.x; acc2[0][1] += a0 * b.y; acc2[0][2] += a0 * b.z; acc2[0][3] += a0 * b.w;
                acc2[1][0] += a1 * b.x; acc2[1][1] += a1 * b.y; acc2[1][2] += a1 * b.z; acc2[1][3] += a1 * b.w;
                acc2[2][0] += a2 * b.x; acc2[2][1] += a2 * b.y; acc2[2][2] += a2 * b.z; acc2[2][3] += a2 * b.w;
                acc2[3][0] += a3 * b.x; acc2[3][1] += a3 * b.y; acc2[3][2] += a3 * b.z; acc2[3][3] += a3 * b.w;
            }
            #pragma unroll
            for (int ss = 0; ss < 4; ss++) {
                int qq0 = ty * 4 + ss;
                float pv = 0.f;
                #pragma unroll
                for (int qq = 0; qq < 4; qq++) pv += acc2[ss][qq] * bufQ[qq0 * 64 + tx * 4 + qq];
                atomicAdd(&w2sqs[qq0], pv);
            }
        }
        __syncthreads();

        if (tid < 64) {
            int qv = tid;
            float w2 = sqrtf(w2sqs[qv]);
            float cosv = w12s[qv] / fmaxf(w1g[i * NL + qv] * w2, EPSV);
            atomicAdd(&ssum, __expf(TEMP2 * cosv));
        }
        __syncthreads();
        if (tid == 0) simg[j * NB + i] = TEMP3 * logf(ssum);

        if (i == j) {
            float* om = out + 1 + (size_t)i * NL * NL;
            for (int n = tid; n < 64 * 64; n += 256) om[n] = bufQ[n];
        }
        __syncthreads();
    }
}

// ---------------------------------------------------------------------------
__global__ void __launch_bounds__(256) loss_kernel(float* __restrict__ out) {
    __shared__ float sm[64][65];
    __shared__ float acc;
    int t = threadIdx.x;
    if (t == 0) acc = 0.f;
    for (int n = t; n < 4096; n += 256) sm[n >> 6][n & 63] = simg[n];
    __syncthreads();
    int g = t >> 2, l = t & 3;
    float mx = -1e30f;
    #pragma unroll
    for (int m = 0; m < 16; m++) mx = fmaxf(mx, sm[g][l * 16 + m]);
    mx = fmaxf(mx, __shfl_xor_sync(0xffffffffu, mx, 1));
    mx = fmaxf(mx, __shfl_xor_sync(0xffffffffu, mx, 2));
    float s = 0.f;
    #pragma unroll
    for (int m = 0; m < 16; m++) s += expf(sm[g][l * 16 + m] - mx);
    s += __shfl_xor_sync(0xffffffffu, s, 1);
    s += __shfl_xor_sync(0xffffffffu, s, 2);
    float lp0 = sm[g][g] - mx - logf(s);

    float mc = -1e30f;
    #pragma unroll
    for (int m = 0; m < 16; m++) mc = fmaxf(mc, sm[l * 16 + m][g]);
    mc = fmaxf(mc, __shfl_xor_sync(0xffffffffu, mc, 1));
    mc = fmaxf(mc, __shfl_xor_sync(0xffffffffu, mc, 2));
    float sc = 0.f;
    #pragma unroll
    for (int m = 0; m < 16; m++) sc += expf(sm[l * 16 + m][g] - mc);
    sc += __shfl_xor_sync(0xffffffffu, sc, 1);
    sc += __shfl_xor_sync(0xffffffffu, sc, 2);
    float lp1 = sm[g][g] - mc - logf(sc);

    if (l == 0) atomicAdd(&acc, lp0 + lp1);
    __syncthreads();
    if (t == 0) out[0] = -acc / (2.0f * (float)NB);
}

// ---------------------------------------------------------------------------
extern "C" void kernel_launch(void* const* d_in, const int* in_sizes, int n_in,
                              void* d_out, int out_size) {
    const float* ecg = (const float*)d_in[0];
    const float* sent = (const float*)d_in[1];
    float* out = (float*)d_out;

    cudaFuncSetAttribute(pair_kernel, cudaFuncAttributeMaxDynamicSharedMemorySize, DSMEM_BYTES);

    convert_kernel<<<2048, 256>>>((const float4*)ecg, (const float4*)sent);
    w1_kernel<<<NB * NL / 8, 256>>>(sent);
    gram_kernel<<<NB, 256>>>(ecg);
    dim3 grid(32, 32);
    pair_kernel<<<grid, 256, DSMEM_BYTES>>>(out);
    loss_kernel<<<1, 256>>>(out);
}

// round 6
// speedup vs baseline: 2.0126x; 1.2736x over previous
#include <cuda_runtime.h>
#include <cuda_fp16.h>
#include <math.h>
#include <stdint.h>

#define NB 64
#define NL 64
#define ND 512
#define TEMP1 4.0f
#define TEMP2 5.0f
#define TEMP3 10.0f
#define EPSV 1e-8f

// ---------------- scratch (__device__ globals; no allocation allowed) -------
__device__ float Gg[NB * NL * NL];
__device__ float w1g[NB * NL];
__device__ float simg[NB * NB];
// fp16 hi/lo splits, k-chunked + ldmatrix-swizzled: [kc(32)][row(4096)][16 halfs]
__device__ __align__(128) __half eh_g[32 * 4096 * 16];
__device__ __align__(128) __half el_g[32 * 4096 * 16];
__device__ __align__(128) __half sh_g[32 * 4096 * 16];
__device__ __align__(128) __half sl_g[32 * 4096 * 16];

// ---------------- PTX helpers (baseline ISA: sm_80/sm_90, no 'a' features) --
__device__ __forceinline__ uint32_t smem_u32(const void* p) {
    return (uint32_t)__cvta_generic_to_shared(p);
}
__device__ __forceinline__ void bulk_cp(uint32_t dst, const void* src, uint32_t bytes, uint32_t mbar) {
    asm volatile("cp.async.bulk.shared::cta.global.mbarrier::complete_tx::bytes [%0], [%1], %2, [%3];"
        :: "r"(dst), "l"(src), "r"(bytes), "r"(mbar) : "memory");
}
#define MBAR_INIT(a, n) asm volatile("mbarrier.init.shared.b64 [%0], %1;" :: "r"(a), "r"(n) : "memory")
#define MBAR_EXPECT_TX(a, tx) asm volatile("mbarrier.arrive.expect_tx.shared.b64 _, [%0], %1;" :: "r"(a), "r"(tx) : "memory")
__device__ __forceinline__ void mbar_wait(uint32_t addr, int phase) {
    asm volatile(
        "{\n\t.reg .pred P;\n\t"
        "W_%=:\n\t"
        "mbarrier.try_wait.parity.acquire.cta.shared::cta.b64 P, [%0], %1, 0x989680;\n\t"
        "@P bra.uni D_%=;\n\t"
        "bra.uni W_%=;\n\t"
        "D_%=:\n\t}"
        :: "r"(addr), "r"(phase) : "memory");
}
__device__ __forceinline__ void ldsm4(uint32_t* r, uint32_t a) {
    asm volatile("ldmatrix.sync.aligned.m8n8.x4.shared.b16 {%0,%1,%2,%3}, [%4];"
        : "=r"(r[0]), "=r"(r[1]), "=r"(r[2]), "=r"(r[3]) : "r"(a));
}
__device__ __forceinline__ void mma16816(float* d, const uint32_t* a, const uint32_t* b) {
    asm volatile(
        "mma.sync.aligned.m16n8k16.row.col.f32.f16.f16.f32 "
        "{%0,%1,%2,%3}, {%4,%5,%6,%7}, {%8,%9}, {%0,%1,%2,%3};"
        : "+f"(d[0]), "+f"(d[1]), "+f"(d[2]), "+f"(d[3])
        : "r"(a[0]), "r"(a[1]), "r"(a[2]), "r"(a[3]), "r"(b[0]), "r"(b[1]));
}

// ---------------------------------------------------------------------------
// convert: fp32 -> fp16 hi + lo, k-chunked layout with baked ldmatrix swizzle.
// thread n: kc = n>>13, r = (n>>1)&4095, s = n&1  (one 16B segment of 8 halfs)
__global__ void __launch_bounds__(256) convert_kernel(const float4* __restrict__ ecg,
                                                      const float4* __restrict__ sent) {
    int n = blockIdx.x * 256 + threadIdx.x;     // 0..262143
    int kc = n >> 13;
    int r  = (n >> 1) & 4095;
    int s  = n & 1;
    int sw = s ^ ((r >> 2) & 1);
    size_t dst = (size_t)kc * 8192 + (size_t)r * 2 + sw;       // uint4 index
    size_t src = ((size_t)r * 512 + (size_t)kc * 16 + (size_t)s * 8) >> 2;  // float4 index

    float4 a0 = ecg[src], a1 = ecg[src + 1];
    uint4 h, l;
    {
        __half2 h2, l2;
        float2 f;
        f = make_float2(a0.x, a0.y); h2 = __float22half2_rn(f);
        l2 = __float22half2_rn(make_float2(f.x - __half2float(h2.x), f.y - __half2float(h2.y)));
        h.x = *(uint32_t*)&h2; l.x = *(uint32_t*)&l2;
        f = make_float2(a0.z, a0.w); h2 = __float22half2_rn(f);
        l2 = __float22half2_rn(make_float2(f.x - __half2float(h2.x), f.y - __half2float(h2.y)));
        h.y = *(uint32_t*)&h2; l.y = *(uint32_t*)&l2;
        f = make_float2(a1.x, a1.y); h2 = __float22half2_rn(f);
        l2 = __float22half2_rn(make_float2(f.x - __half2float(h2.x), f.y - __half2float(h2.y)));
        h.z = *(uint32_t*)&h2; l.z = *(uint32_t*)&l2;
        f = make_float2(a1.z, a1.w); h2 = __float22half2_rn(f);
        l2 = __float22half2_rn(make_float2(f.x - __half2float(h2.x), f.y - __half2float(h2.y)));
        h.w = *(uint32_t*)&h2; l.w = *(uint32_t*)&l2;
    }
    ((uint4*)eh_g)[dst] = h;
    ((uint4*)el_g)[dst] = l;

    float4 b0 = sent[src], b1 = sent[src + 1];
    {
        __half2 h2, l2;
        float2 f;
        f = make_float2(b0.x, b0.y); h2 = __float22half2_rn(f);
        l2 = __float22half2_rn(make_float2(f.x - __half2float(h2.x), f.y - __half2float(h2.y)));
        h.x = *(uint32_t*)&h2; l.x = *(uint32_t*)&l2;
        f = make_float2(b0.z, b0.w); h2 = __float22half2_rn(f);
        l2 = __float22half2_rn(make_float2(f.x - __half2float(h2.x), f.y - __half2float(h2.y)));
        h.y = *(uint32_t*)&h2; l.y = *(uint32_t*)&l2;
        f = make_float2(b1.x, b1.y); h2 = __float22half2_rn(f);
        l2 = __float22half2_rn(make_float2(f.x - __half2float(h2.x), f.y - __half2float(h2.y)));
        h.z = *(uint32_t*)&h2; l.z = *(uint32_t*)&l2;
        f = make_float2(b1.z, b1.w); h2 = __float22half2_rn(f);
        l2 = __float22half2_rn(make_float2(f.x - __half2float(h2.x), f.y - __half2float(h2.y)));
        h.w = *(uint32_t*)&h2; l.w = *(uint32_t*)&l2;
    }
    ((uint4*)sh_g)[dst] = h;
    ((uint4*)sl_g)[dst] = l;
}

// ---------------------------------------------------------------------------
__global__ void w1_kernel(const float* __restrict__ sent) {
    int row = blockIdx.x * 8 + (threadIdx.x >> 5);
    int lane = threadIdx.x & 31;
    const float* p = sent + (size_t)row * ND;
    float s = 0.f;
    #pragma unroll
    for (int d = lane; d < ND; d += 32) { float v = p[d]; s += v * v; }
    #pragma unroll
    for (int o = 16; o; o >>= 1) s += __shfl_xor_sync(0xffffffffu, s, o);
    if (lane == 0) w1g[row] = sqrtf(s);
}

// ---------------------------------------------------------------------------
__global__ void __launch_bounds__(256) gram_kernel(const float* __restrict__ ecg) {
    __shared__ float tile[64][68];
    int j = blockIdx.x;
    int tid = threadIdx.x;
    int tx = tid & 15, ty = tid >> 4;
    const float* E = ecg + (size_t)j * NL * ND;

    float acc[4][4] = {};
    for (int kc = 0; kc < ND; kc += 64) {
        __syncthreads();
        for (int n = tid; n < 64 * 64; n += 256) {
            int r = n >> 6, d = n & 63;
            tile[d][r] = E[r * ND + kc + d];
        }
        __syncthreads();
        #pragma unroll 8
        for (int d = 0; d < 64; d++) {
            float4 a = *(const float4*)&tile[d][ty * 4];
            float4 b = *(const float4*)&tile[d][tx * 4];
            acc[0][0] += a.x * b.x; acc[0][1] += a.x * b.y; acc[0][2] += a.x * b.z; acc[0][3] += a.x * b.w;
            acc[1][0] += a.y * b.x; acc[1][1] += a.y * b.y; acc[1][2] += a.y * b.z; acc[1][3] += a.y * b.w;
            acc[2][0] += a.z * b.x; acc[2][1] += a.z * b.y; acc[2][2] += a.z * b.z; acc[2][3] += a.z * b.w;
            acc[3][0] += a.w * b.x; acc[3][1] += a.w * b.y; acc[3][2] += a.w * b.z; acc[3][3] += a.w * b.w;
        }
    }
    float* Gj = Gg + (size_t)j * NL * NL;
    #pragma unroll
    for (int ss = 0; ss < 4; ss++)
        #pragma unroll
        for (int qq = 0; qq < 4; qq++)
            Gj[(ty * 4 + ss) * NL + tx * 4 + qq] = acc[ss][qq];
}

// ---------------------------------------------------------------------------
// pair_kernel: CTA = (bi, bj); 128 ecg rows x 128 sent rows. fp16x3 mma GEMM
// with cp.async.bulk staged loads, then fused epilogue for 4 (i,j) pairs.
#define STAGE 16384
#define SROW 133
#define DSMEM_BYTES (2 * STAGE + 128 * SROW * 4)

__global__ void __launch_bounds__(256, 2) pair_kernel(float* __restrict__ out) {
    extern __shared__ char dsm[];
    __shared__ uint64_t full_mb[2];
    __shared__ float w12s[64];
    __shared__ float w2sqs[64];
    __shared__ float ssum;

    uint32_t base = smem_u32(dsm);
    float* S    = (float*)(dsm + 2 * STAGE);    // 128 x 133 fp32
    float* bufG = (float*)dsm;                  // 64 x 64 (overlays stage 0)
    float* bufQ = (float*)(dsm + STAGE);        // 64 x 64 (overlays stage 1)

    int tid = threadIdx.x;
    int wid = tid >> 5, lane = tid & 31;
    int bi = blockIdx.x, bj = blockIdx.y;
    int wm = wid & 1, wn = wid >> 1;

    const char* ehp = (const char*)eh_g;
    const char* elp = (const char*)el_g;
    const char* shp = (const char*)sh_g;
    const char* slp = (const char*)sl_g;
    size_t aoff = (size_t)bj * 4096;    // byte offset of 128-row slice within a kc block
    size_t boff = (size_t)bi * 4096;

    // ldmatrix lane offsets (swizzle baked in gmem: seg ^= (row>>2)&1, 32B rows)
    int q4 = lane >> 3;
    int ar = (lane & 7) + (q4 & 1) * 8;
    int as = q4 >> 1;
    uint32_t offA = (uint32_t)((wm * 64 + ar) * 32 + ((as ^ ((ar >> 2) & 1)) * 16));
    int br = (lane & 7) + ((q4 >> 1) & 1) * 8;
    int bs = q4 & 1;
    uint32_t offB = (uint32_t)((wn * 32 + br) * 32 + ((bs ^ ((br >> 2) & 1)) * 16));

    uint32_t mb0 = smem_u32(&full_mb[0]);
    uint32_t mb1 = smem_u32(&full_mb[1]);

    if (tid == 0) {
        MBAR_INIT(mb0, 1);
        MBAR_INIT(mb1, 1);
    }
    __syncthreads();

    auto fill = [&](uint32_t st, uint32_t mb, int kc) {
        size_t blk = (size_t)kc * 131072;   // kc block = 4096 rows * 32B
        MBAR_EXPECT_TX(mb, STAGE);
        bulk_cp(st,          ehp + blk + aoff, 4096, mb);
        bulk_cp(st + 4096,   elp + blk + aoff, 4096, mb);
        bulk_cp(st + 8192,   shp + blk + boff, 4096, mb);
        bulk_cp(st + 12288,  slp + blk + boff, 4096, mb);
    };

    if (tid == 0) {
        fill(base, mb0, 0);
        fill(base + STAGE, mb1, 1);
    }

    float acc[4][4][4] = {};

    for (int c = 0; c < 32; c++) {
        uint32_t st = base + (uint32_t)(c & 1) * STAGE;
        uint32_t mb = (c & 1) ? mb1 : mb0;
        mbar_wait(mb, (c >> 1) & 1);

        uint32_t af[4][4], al[4][4], bh[2][4], bl[2][4];
        ldsm4(bh[0], st + 8192 + offB);
        ldsm4(bh[1], st + 8192 + offB + 512);
        ldsm4(bl[0], st + 12288 + offB);
        ldsm4(bl[1], st + 12288 + offB + 512);
        #pragma unroll
        for (int f = 0; f < 4; f++) ldsm4(af[f], st + offA + f * 512);
        #pragma unroll
        for (int f = 0; f < 4; f++) ldsm4(al[f], st + 4096 + offA + f * 512);

        __syncthreads();   // all warps finished reading this stage
        if (tid == 0 && c + 2 < 32) fill(st, mb, c + 2);

        #pragma unroll
        for (int f = 0; f < 4; f++)
            #pragma unroll
            for (int g = 0; g < 4; g++) {
                mma16816(acc[f][g], af[f], &bh[g >> 1][(g & 1) * 2]);
                mma16816(acc[f][g], af[f], &bl[g >> 1][(g & 1) * 2]);
                mma16816(acc[f][g], al[f], &bh[g >> 1][(g & 1) * 2]);
            }
    }

    // ---- write S (scores, fp32) to smem
    {
        int r0 = lane >> 2, c0 = (lane & 3) * 2;
        #pragma unroll
        for (int f = 0; f < 4; f++)
            #pragma unroll
            for (int g = 0; g < 4; g++) {
                float* p = S + (size_t)(wm * 64 + f * 16 + r0) * SROW + wn * 32 + g * 8 + c0;
                p[0] = acc[f][g][0];
                p[1] = acc[f][g][1];
                p[8 * SROW] = acc[f][g][2];
                p[8 * SROW + 1] = acc[f][g][3];
            }
    }
    __syncthreads();

    // ---- epilogue: 4 (i,j) pairs
    int tx = tid & 15, ty = tid >> 4;
    for (int p = 0; p < 4; p++) {
        int jh = p >> 1, ih = p & 1;
        int i = 2 * bi + ih;
        int j = 2 * bj + jh;
        const float* Sp = S + (size_t)(64 * jh) * SROW + 64 * ih;  // S[s][q]

        if (ih == 0) {
            const float* Gj = Gg + (size_t)j * NL * NL;
            for (int n = tid; n < 64 * 64; n += 256) bufG[n] = Gj[n];
        }
        if (tid < 64) w2sqs[tid] = 0.f;
        if (tid == 0) ssum = 0.f;
        __syncthreads();

        // softmax 1 over q (per row s): attn1[s][q] -> bufQ
        {
            int g = tid >> 2, l = tid & 3;
            float v[16];
            float mx = -1e30f;
            #pragma unroll
            for (int m = 0; m < 16; m++) { v[m] = Sp[g * SROW + l * 16 + m]; mx = fmaxf(mx, v[m]); }
            mx = fmaxf(mx, __shfl_xor_sync(0xffffffffu, mx, 1));
            mx = fmaxf(mx, __shfl_xor_sync(0xffffffffu, mx, 2));
            float sm = 0.f;
            #pragma unroll
            for (int m = 0; m < 16; m++) { v[m] = __expf(v[m] - mx); sm += v[m]; }
            sm += __shfl_xor_sync(0xffffffffu, sm, 1);
            sm += __shfl_xor_sync(0xffffffffu, sm, 2);
            float inv = 1.f / sm;
            #pragma unroll
            for (int m = 0; m < 16; m++) bufQ[g * 64 + l * 16 + m] = v[m] * inv;
        }
        __syncthreads();

        // softmax 2 over s (transposed): A[q][s] -> bufQ, plus w12
        float e[16];
        float invs;
        {
            int q = tid >> 2, l = tid & 3;
            float mx = -1e30f;
            #pragma unroll
            for (int m = 0; m < 16; m++) { e[m] = TEMP1 * bufQ[(l * 16 + m) * 64 + q]; mx = fmaxf(mx, e[m]); }
            mx = fmaxf(mx, __shfl_xor_sync(0xffffffffu, mx, 1));
            mx = fmaxf(mx, __shfl_xor_sync(0xffffffffu, mx, 2));
            float sm = 0.f;
            #pragma unroll
            for (int m = 0; m < 16; m++) { e[m] = __expf(e[m] - mx); sm += e[m]; }
            sm += __shfl_xor_sync(0xffffffffu, sm, 1);
            sm += __shfl_xor_sync(0xffffffffu, sm, 2);
            invs = 1.f / sm;
        }
        __syncthreads();
        {
            int q = tid >> 2, l = tid & 3;
            float w12p = 0.f;
            #pragma unroll
            for (int m = 0; m < 16; m++) {
                int s = l * 16 + m;
                float a = e[m] * invs;
                bufQ[q * 64 + s] = a;
                w12p += a * Sp[s * SROW + q];
            }
            w12p += __shfl_xor_sync(0xffffffffu, w12p, 1);
            w12p += __shfl_xor_sync(0xffffffffu, w12p, 2);
            if (l == 0) w12s[q] = w12p;
        }
        __syncthreads();

        // w2sq[q] = diag(A G A^T)
        {
            float acc2[4][4] = {};
            #pragma unroll 8
            for (int u = 0; u < 64; u++) {
                float a0 = bufQ[(ty * 4 + 0) * 64 + u];
                float a1 = bufQ[(ty * 4 + 1) * 64 + u];
                float a2 = bufQ[(ty * 4 + 2) * 64 + u];
                float a3 = bufQ[(ty * 4 + 3) * 64 + u];
                float4 b = *(const float4*)&bufG[u * 64 + tx * 4];
                acc2[0][0] += a0 * b.x; acc2[0][1] += a0 * b.y; acc2[0][2] += a0 * b.z; acc2[0][3] += a0 * b.w;
                acc2[1][0] += a1 * b.x; acc2[1][1] += a1 * b.y; acc2[1][2] += a1 * b.z; acc2[1][3] += a1 * b.w;
                acc2[2][0] += a2 * b.x; acc2[2][1] += a2 * b.y; acc2[2][2] += a2 * b.z; acc2[2][3] += a2 * b.w;
                acc2[3][0] += a3 * b.x; acc2[3][1] += a3 * b.y; acc2[3][2] += a3 * b.z; acc2[3][3] += a3 * b.w;
            }
            #pragma unroll
            for (int ss = 0; ss < 4; ss++) {
                int qq0 = ty * 4 + ss;
                float pv = 0.f;
                #pragma unroll
                for (int qq = 0; qq < 4; qq++) pv += acc2[ss][qq] * bufQ[qq0 * 64 + tx * 4 + qq];
                atomicAdd(&w2sqs[qq0], pv);
            }
        }
        __syncthreads();

        if (tid < 64) {
            int qv = tid;
            float w2 = sqrtf(w2sqs[qv]);
            float cosv = w12s[qv] / fmaxf(w1g[i * NL + qv] * w2, EPSV);
            atomicAdd(&ssum, __expf(TEMP2 * cosv));
        }
        __syncthreads();
        if (tid == 0) simg[j * NB + i] = TEMP3 * logf(ssum);

        if (i == j) {
            float* om = out + 1 + (size_t)i * NL * NL;
            for (int n = tid; n < 64 * 64; n += 256) om[n] = bufQ[n];
        }
        __syncthreads();
    }
}

// ---------------------------------------------------------------------------
__global__ void __launch_bounds__(256) loss_kernel(float* __restrict__ out) {
    __shared__ float sm[64][65];
    __shared__ float acc;
    int t = threadIdx.x;
    if (t == 0) acc = 0.f;
    for (int n = t; n < 4096; n += 256) sm[n >> 6][n & 63] = simg[n];
    __syncthreads();
    int g = t >> 2, l = t & 3;
    float mx = -1e30f;
    #pragma unroll
    for (int m = 0; m < 16; m++) mx = fmaxf(mx, sm[g][l * 16 + m]);
    mx = fmaxf(mx, __shfl_xor_sync(0xffffffffu, mx, 1));
    mx = fmaxf(mx, __shfl_xor_sync(0xffffffffu, mx, 2));
    float s = 0.f;
    #pragma unroll
    for (int m = 0; m < 16; m++) s += expf(sm[g][l * 16 + m] - mx);
    s += __shfl_xor_sync(0xffffffffu, s, 1);
    s += __shfl_xor_sync(0xffffffffu, s, 2);
    float lp0 = sm[g][g] - mx - logf(s);

    float mc = -1e30f;
    #pragma unroll
    for (int m = 0; m < 16; m++) mc = fmaxf(mc, sm[l * 16 + m][g]);
    mc = fmaxf(mc, __shfl_xor_sync(0xffffffffu, mc, 1));
    mc = fmaxf(mc, __shfl_xor_sync(0xffffffffu, mc, 2));
    float sc = 0.f;
    #pragma unroll
    for (int m = 0; m < 16; m++) sc += expf(sm[l * 16 + m][g] - mc);
    sc += __shfl_xor_sync(0xffffffffu, sc, 1);
    sc += __shfl_xor_sync(0xffffffffu, sc, 2);
    float lp1 = sm[g][g] - mc - logf(sc);

    if (l == 0) atomicAdd(&acc, lp0 + lp1);
    __syncthreads();
    if (t == 0) out[0] = -acc / (2.0f * (float)NB);
}

// ---------------------------------------------------------------------------
extern "C" void kernel_launch(void* const* d_in, const int* in_sizes, int n_in,
                              void* d_out, int out_size) {
    const float* ecg = (const float*)d_in[0];
    const float* sent = (const float*)d_in[1];
    float* out = (float*)d_out;

    cudaFuncSetAttribute(pair_kernel, cudaFuncAttributeMaxDynamicSharedMemorySize, DSMEM_BYTES);

    convert_kernel<<<1024, 256>>>((const float4*)ecg, (const float4*)sent);
    w1_kernel<<<NB * NL / 8, 256>>>(sent);
    gram_kernel<<<NB, 256>>>(ecg);
    dim3 grid(32, 32);
    pair_kernel<<<grid, 256, DSMEM_BYTES>>>(out);
    loss_kernel<<<1, 256>>>(out);
}